// round 13
// baseline (speedup 1.0000x reference)
#include <cuda_runtime.h>
#include <cuda_bf16.h>
#include <math.h>
#include <stdint.h>

// ArcFace loss. B=512, F=128, C=100000.
// R10 skeleton, GEMM moved to FP8 e4m3 mma.sync.m16n8k32 (2x tensor rate,
// half the ldmatrix/STS traffic). Operands scaled x16; descale (1/256) folded
// into the exp argument for free. Target-column path stays exact fp32.

#define FF 128
#define BB 512
#define BN 256
#define NCTA 148

__device__ float g_part[1600 * 512];  // [slot = bx*4 + wn][row]
__device__ float g_margin[BB];
__device__ float g_adj[BB];
__device__ float g_rowv[BB];
__device__ uint4 g_Apack[4096];       // permuted e4m3 A fragments (64KB)

// smem: B 2 x (256 n-rows x 144B)  ([n][k] fp8, 16B pad -> conflict-free ldsm)
#define BSTRIDE 144
#define BSZ     (256 * BSTRIDE)      // 36864
#define SM_B    0
#define SM_TOTAL (2 * BSZ)           // 73728

// exp argument scale: logits carry x256 from the fp8 x16 operand scaling
#define KEXP 0.0056355275034725135f  // log2(e) / 256

__device__ __forceinline__ uint32_t smem_u32(const void* p) {
    uint32_t a;
    asm("{ .reg .u64 t; cvta.to.shared.u64 t, %1; cvt.u32.u64 %0, t; }"
        : "=r"(a) : "l"(p));
    return a;
}
__device__ __forceinline__ void ldsm4(uint32_t* r, uint32_t addr) {
    asm volatile("ldmatrix.sync.aligned.m8n8.x4.shared.b16 {%0,%1,%2,%3}, [%4];"
                 : "=r"(r[0]), "=r"(r[1]), "=r"(r[2]), "=r"(r[3]) : "r"(addr));
}
__device__ __forceinline__ void mma8(float* d, uint32_t a0, uint32_t a1,
                                     uint32_t a2, uint32_t a3,
                                     uint32_t b0, uint32_t b1) {
    asm volatile(
        "mma.sync.aligned.m16n8k32.row.col.f32.e4m3.e4m3.f32 "
        "{%0,%1,%2,%3}, {%4,%5,%6,%7}, {%8,%9}, {%0,%1,%2,%3};"
        : "+f"(d[0]), "+f"(d[1]), "+f"(d[2]), "+f"(d[3])
        : "r"(a0), "r"(a1), "r"(a2), "r"(a3), "r"(b0), "r"(b1));
}
// pack 4 floats -> 4 e4m3 bytes (a0 = lowest byte)
__device__ __forceinline__ uint32_t fp8x4(float a0, float a1, float a2, float a3) {
    uint16_t lo, hi;
    asm("cvt.rn.satfinite.e4m3x2.f32 %0, %1, %2;" : "=h"(lo) : "f"(a1), "f"(a0));
    asm("cvt.rn.satfinite.e4m3x2.f32 %0, %1, %2;" : "=h"(hi) : "f"(a3), "f"(a2));
    return (uint32_t)lo | ((uint32_t)hi << 16);
}
__device__ __forceinline__ float ex2a(float z) {     // MUFU EX2
    float r;
    asm("ex2.approx.ftz.f32 %0, %1;" : "=f"(r) : "f"(z));
    return r;
}
// FMA-pipe 2^z (deg-6, exact at 0)
__device__ __forceinline__ float fexp2(float z) {
    float n = rintf(z);
    float f = z - n;
    float p = 1.5403530393381606e-4f;
    p = fmaf(p, f, 1.3333558146428443e-3f);
    p = fmaf(p, f, 9.6181291076284770e-3f);
    p = fmaf(p, f, 5.5504108664821580e-2f);
    p = fmaf(p, f, 2.4022650695910070e-1f);
    p = fmaf(p, f, 6.9314718055994530e-1f);
    p = fmaf(p, f, 1.0f);
    return __int_as_float(__float_as_int(p) + ((int)n << 23));
}
__device__ __forceinline__ int load_target(const void* tptr, int b, int C) {
    const int* p = (const int*)tptr;
    bool is64 = ((p[1] | p[3] | p[5] | p[7] | p[9]) == 0);
    long long t = is64 ? ((const long long*)tptr)[b] : (long long)p[b];
    if (t < 0) t = 0;
    if (t >= C) t = C - 1;
    return (int)t;
}

// ======== pre-kernel: A -> fragment-permuted e4m3 (x16 scaled) ========
// quad i = mc*1024 + wm*256 + mi*128 + ks*32 + lane   (4096 quads)
// m16n8k32 A frag: r0 = mc*128+wm*32+mi*16+lane/4, r1 = r0+8,
// kb = ks*32+(lane%4)*4; q = {r0[kb..+3], r1[kb..+3], r0[kb+16..+19], r1[kb+16..+19]}
__global__ void precvt_A8(const float* __restrict__ feat) {
    int i = blockIdx.x * 256 + threadIdx.x;     // 0..4095
    int lane = i & 31, ks = (i >> 5) & 3, mi = (i >> 7) & 1;
    int wm = (i >> 8) & 3, mc = (i >> 10) & 3;
    int r0 = mc * 128 + wm * 32 + mi * 16 + (lane >> 2);
    int r1 = r0 + 8;
    int kb = ks * 32 + (lane & 3) * 4;
    const float* f0 = feat + r0 * FF;
    const float* f1 = feat + r1 * FF;
    uint4 q;
    q.x = fp8x4(f0[kb]    * 16.f, f0[kb+1]  * 16.f, f0[kb+2]  * 16.f, f0[kb+3]  * 16.f);
    q.y = fp8x4(f1[kb]    * 16.f, f1[kb+1]  * 16.f, f1[kb+2]  * 16.f, f1[kb+3]  * 16.f);
    q.z = fp8x4(f0[kb+16] * 16.f, f0[kb+17] * 16.f, f0[kb+18] * 16.f, f0[kb+19] * 16.f);
    q.w = fp8x4(f1[kb+16] * 16.f, f1[kb+17] * 16.f, f1[kb+18] * 16.f, f1[kb+19] * 16.f);
    g_Apack[i] = q;
}

// ======== B chunk (32 k-rows, all 256 n): LDG / cvt+STS split ========
// thread block map: kb = (tid>>6)*4 (k within chunk), nb = (tid&63)*4
__device__ __forceinline__ void ldg_B8(float4* vh, const float* __restrict__ w,
                                       int m, int c0, int C, int tid) {
    const float4* w4 = (const float4*)w;
    int kb = (tid >> 6) * 4, nb = (tid & 63) * 4;
    int c = c0 + nb;
    #pragma unroll
    for (int j = 0; j < 4; j++) {
        vh[j] = make_float4(0.f, 0.f, 0.f, 0.f);
        if (c < C)                            // C % 4 == 0 -> all-or-nothing
            vh[j] = w4[((size_t)(m * 32 + kb + j) * (size_t)C + (size_t)c) >> 2];
    }
}
__device__ __forceinline__ void sts_B8(const float4* vh, char* smem, int buf,
                                       int m, int tid) {
    char* base = smem + SM_B + buf * BSZ;
    int kb = (tid >> 6) * 4, nb = (tid & 63) * 4;
    const float* v = (const float*)vh;        // v[j*4 + nn]
    #pragma unroll
    for (int nn = 0; nn < 4; nn++) {
        uint32_t pk = fp8x4(v[0 + nn] * 16.f, v[4 + nn] * 16.f,
                            v[8 + nn] * 16.f, v[12 + nn] * 16.f);
        *(uint32_t*)(base + (nb + nn) * BSTRIDE + m * 32 + kb) = pk;
    }
}

// ================= persistent fused kernel =================
__global__ void __launch_bounds__(512, 1)
fused_kernel(const float* __restrict__ feat, const float* __restrict__ w,
             const void* __restrict__ target, int C, int NT) {
    extern __shared__ char smem[];
    const int tid  = threadIdx.x;
    const int wid  = tid >> 5;
    const int lane = tid & 31;
    const int bid  = blockIdx.x;
    const int wm   = wid >> 2;            // warp row group (32 rows in m-chunk)
    const int wn   = wid & 3;             // warp col group (64 cols)
    const uint32_t sb = smem_u32(smem);

    const int niter = (NT - bid + NCTA - 1) / NCTA;

    // ---- prologue: first B tile + aux ----
    {
        float4 vh[4];
        #pragma unroll
        for (int m = 0; m < 4; m++) {
            ldg_B8(vh, w, m, bid * BN, C, tid);
            sts_B8(vh, smem, 0, m, tid);
        }
    }
    // aux: exact-fp32 target-column math (CTAs 0..127, 4 warps each)
    if (bid < 128 && wid < 4) {
        int b = bid * 4 + wid;
        int t = load_target(target, b, C);
        float fsq = 0.f, wsq = 0.f, dot = 0.f;
        #pragma unroll
        for (int q = 0; q < 4; q++) {
            int f = lane + q * 32;
            float fv = feat[b * FF + f];
            float wv = w[(size_t)f * (size_t)C + (size_t)t];
            fsq = fmaf(fv, fv, fsq);
            wsq = fmaf(wv, wv, wsq);
            dot = fmaf(fv, wv, dot);
        }
        const unsigned msk = 0xffffffffu;
        #pragma unroll
        for (int o = 16; o > 0; o >>= 1) {
            fsq += __shfl_down_sync(msk, fsq, o);
            wsq += __shfl_down_sync(msk, wsq, o);
            dot += __shfl_down_sync(msk, dot, o);
        }
        if (lane == 0) {
            float modulus = sqrtf(fsq) * sqrtf(wsq);
            float ct = dot / (modulus * 1.01f);
            ct = fminf(1.0f, fmaxf(-1.0f, ct));
            float ml = modulus * cosf(acosf(ct) + 0.5f);  // ANGLE=0.5
            g_margin[b] = ml;
            g_adj[b] = expf(ml) - expf(dot);
        }
    }
    __syncthreads();

    // B ldmatrix lane base: tile g = lane>>3 of x4:
    //   n = wn*64 + p*16 + ((g>>1)<<3) + (lane&7),  k-chunk = ks*2 + (g&1)
    const int bg = lane >> 3, blr = lane & 7;
    const uint32_t b_lb = (uint32_t)((wn * 64 + ((bg >> 1) << 3) + blr) * BSTRIDE
                                     + ((bg & 1) << 4));

    const uint4* __restrict__ Ap = g_Apack;

    int cur = 0;
    for (int it = 0; it < niter; it++) {
        const int bx = bid + it * NCTA;
        const bool have_next = (it + 1 < niter);
        const int nc0 = (bx + NCTA) * BN;
        const uint32_t bbase = sb + SM_B + cur * BSZ;

        for (int m = 0; m < 4; m++) {
            float4 vh[4];
            if (have_next)
                ldg_B8(vh, w, m, nc0, C, tid);   // LDG early: lands behind MMA

            const int qb = m * 1024 + wm * 256 + lane;

            float acc[2][8][4];
            #pragma unroll
            for (int mi = 0; mi < 2; mi++)
                #pragma unroll
                for (int j = 0; j < 8; j++)
                    #pragma unroll
                    for (int q = 0; q < 4; q++) acc[mi][j][q] = 0.0f;

            #pragma unroll
            for (int ks = 0; ks < 4; ks++) {
                uint4 af0 = Ap[qb + ks * 32];          // mi=0
                uint4 af1 = Ap[qb + 128 + ks * 32];    // mi=1
                #pragma unroll
                for (int p = 0; p < 4; p++) {          // np pairs
                    uint32_t bfr[4];
                    ldsm4(bfr, bbase + b_lb + (uint32_t)(p * 16 * BSTRIDE + ks * 32));
                    mma8(acc[0][2*p+0], af0.x, af0.y, af0.z, af0.w, bfr[0], bfr[1]);
                    mma8(acc[0][2*p+1], af0.x, af0.y, af0.z, af0.w, bfr[2], bfr[3]);
                    mma8(acc[1][2*p+0], af1.x, af1.y, af1.z, af1.w, bfr[0], bfr[1]);
                    mma8(acc[1][2*p+1], af1.x, af1.y, af1.z, af1.w, bfr[2], bfr[3]);
                }
            }

            // epilogue: exp(acc/256) hybrid (5/8 MUFU, 3/8 FMA) + row sums
            const unsigned msk = 0xffffffffu;
            float* slot = &g_part[(size_t)(bx * 4 + wn) * 512];
            #pragma unroll
            for (int mi = 0; mi < 2; mi++) {
                float s0 = 0.f, s1 = 0.f;
                #pragma unroll
                for (int j = 0; j < 8; j++) {
                    float z0 = acc[mi][j][0] * KEXP;
                    float z1 = acc[mi][j][1] * KEXP;
                    float z2 = acc[mi][j][2] * KEXP;
                    float z3 = acc[mi][j][3] * KEXP;
                    s0 += ex2a(z0);                       // MUFU
                    s1 += ex2a(z2);                       // MUFU
                    if (j < 2) { s0 += ex2a(z1);  s1 += ex2a(z3);  }
                    else       { s0 += fexp2(z1); s1 += fexp2(z3); }
                }
                s0 += __shfl_xor_sync(msk, s0, 1);
                s0 += __shfl_xor_sync(msk, s0, 2);
                s1 += __shfl_xor_sync(msk, s1, 1);
                s1 += __shfl_xor_sync(msk, s1, 2);
                if ((lane & 3) == 0) {
                    int g = lane >> 2;
                    int grow = m * 128 + wm * 32 + mi * 16 + g;
                    slot[grow]     = s0;
                    slot[grow + 8] = s1;
                }
            }

            if (have_next)
                sts_B8(vh, smem, cur ^ 1, m, tid);   // STS late
        }
        __syncthreads();                  // ONE barrier per tile (B swap)
        cur ^= 1;
    }
}

// ================= finalize 1: per-row value =================
__global__ void finalize1_kernel(int NSLOT, float pad) {
    int row = blockIdx.x;        // 0..511
    int j = threadIdx.x;         // 0..127
    float s = 0.f;
    for (int t = j; t < NSLOT; t += 128)      // fixed order -> deterministic
        s += g_part[(size_t)t * 512 + row];
    __shared__ float red[128];
    red[j] = s;
    __syncthreads();
    #pragma unroll
    for (int o = 64; o > 0; o >>= 1) {
        if (j < o) red[j] += red[j + o];
        __syncthreads();
    }
    if (j == 0) {
        float down = red[0] - pad + g_adj[row];
        g_rowv[row] = logf(down) - g_margin[row];
    }
}

// ================= finalize 2: scalar =================
__global__ void finalize2_kernel(float* __restrict__ out) {
    int b = threadIdx.x;         // 0..511
    __shared__ float red[BB];
    red[b] = g_rowv[b];
    __syncthreads();
    #pragma unroll
    for (int o = BB / 2; o > 0; o >>= 1) {
        if (b < o) red[b] += red[b + o];
        __syncthreads();
    }
    if (b == 0) out[0] = red[0] / (float)BB;
}

// ================= launch =================
extern "C" void kernel_launch(void* const* d_in, const int* in_sizes, int n_in,
                              void* d_out, int out_size) {
    const float* feat = (const float*)d_in[0];
    const float* w    = (const float*)d_in[1];
    const void*  target = d_in[2];
    float* out = (float*)d_out;

    int C  = in_sizes[1] / FF;               // 100000
    int NT = (C + BN - 1) / BN;              // 391
    float pad = (float)(NT * BN - C);        // 96

    cudaFuncSetAttribute(fused_kernel,
                         cudaFuncAttributeMaxDynamicSharedMemorySize, SM_TOTAL);

    precvt_A8<<<16, 256>>>(feat);
    fused_kernel<<<NCTA, 512, SM_TOTAL>>>(feat, w, target, C, NT);
    finalize1_kernel<<<BB, 128>>>(4 * NT, pad);
    finalize2_kernel<<<1, BB>>>(out);
}

// round 14
// speedup vs baseline: 1.0856x; 1.0856x over previous
#include <cuda_runtime.h>
#include <cuda_bf16.h>
#include <math.h>
#include <stdint.h>

// ArcFace loss. B=512, F=128, C=100000.
// R10 bf16 core (best: 65.6us) fused into ONE launch: A-pack prologue,
// persistent GEMM+exp, and both finalize stages joined by grid-wide spin
// barriers (grid = 148 = 1 CTA/SM -> co-resident -> deadlock-free).
// Counters reset by CTA0 at the very end => graph-replay deterministic.

#define FF 128
#define BB 512
#define BN 256
#define NCTA 148

__device__ float g_part[1600 * 512];  // [slot = bx*4 + wn][row]
__device__ float g_margin[BB];
__device__ float g_adj[BB];
__device__ float g_rowv[BB];
__device__ uint4 g_Apack[8192];       // permuted bf16 A fragments (128KB)
__device__ volatile unsigned g_cnt[3];  // grid barrier counters (zero-init)

// smem: B 2x(128 k-rows x 528B)
#define BSTRIDE 528
#define BSZ     (128 * BSTRIDE)      // 67584
#define SM_B    0
#define SM_TOTAL (2 * BSZ)           // 135168

__device__ __forceinline__ uint32_t smem_u32(const void* p) {
    uint32_t a;
    asm("{ .reg .u64 t; cvta.to.shared.u64 t, %1; cvt.u32.u64 %0, t; }"
        : "=r"(a) : "l"(p));
    return a;
}
__device__ __forceinline__ void ldsm4t(uint32_t* r, uint32_t addr) {
    asm volatile("ldmatrix.sync.aligned.m8n8.x4.trans.shared.b16 {%0,%1,%2,%3}, [%4];"
                 : "=r"(r[0]), "=r"(r[1]), "=r"(r[2]), "=r"(r[3]) : "r"(addr));
}
__device__ __forceinline__ void mma4(float* d, uint32_t a0, uint32_t a1,
                                     uint32_t a2, uint32_t a3,
                                     uint32_t b0, uint32_t b1) {
    asm volatile(
        "mma.sync.aligned.m16n8k16.row.col.f32.bf16.bf16.f32 "
        "{%0,%1,%2,%3}, {%4,%5,%6,%7}, {%8,%9}, {%0,%1,%2,%3};"
        : "+f"(d[0]), "+f"(d[1]), "+f"(d[2]), "+f"(d[3])
        : "r"(a0), "r"(a1), "r"(a2), "r"(a3), "r"(b0), "r"(b1));
}
__device__ __forceinline__ uint32_t pack_bf16x2(float lo, float hi) {
    __nv_bfloat162 p = __floats2bfloat162_rn(lo, hi);
    return *(uint32_t*)&p;
}
// FMA-pipe exp (deg-6, exact at 0).
__device__ __forceinline__ float fast_exp(float x) {
    float z = x * 1.4426950408889634f;
    float n = rintf(z);
    float f = z - n;
    float p = 1.5403530393381606e-4f;
    p = fmaf(p, f, 1.3333558146428443e-3f);
    p = fmaf(p, f, 9.6181291076284770e-3f);
    p = fmaf(p, f, 5.5504108664821580e-2f);
    p = fmaf(p, f, 2.4022650695910070e-1f);
    p = fmaf(p, f, 6.9314718055994530e-1f);
    p = fmaf(p, f, 1.0f);
    return __int_as_float(__float_as_int(p) + ((int)n << 23));
}
__device__ __forceinline__ int load_target(const void* tptr, int b, int C) {
    const int* p = (const int*)tptr;
    bool is64 = ((p[1] | p[3] | p[5] | p[7] | p[9]) == 0);
    long long t = is64 ? ((const long long*)tptr)[b] : (long long)p[b];
    if (t < 0) t = 0;
    if (t >= C) t = C - 1;
    return (int)t;
}

// ---- grid barrier primitives (1 CTA/SM persistent grid) ----
__device__ __forceinline__ void gbar_arrive(int k) {
    __syncthreads();
    if (threadIdx.x == 0) {
        __threadfence();                              // release
        atomicAdd((unsigned*)&g_cnt[k], 1u);
    }
}
__device__ __forceinline__ void gbar_spin(int k) {
    if (threadIdx.x == 0) {
        while (g_cnt[k] < (unsigned)NCTA) __nanosleep(128);
        __threadfence();                              // acquire
    }
    __syncthreads();
}

// ======== B chunk: split LDG / STS (R10-proven) ========
__device__ __forceinline__ void ldg_B(float4* vh, const float* __restrict__ w,
                                      int m, int c0, int C, int tid) {
    const float4* w4 = (const float4*)w;
    #pragma unroll
    for (int i = 0; i < 4; i++) {
        int idx = i * 512 + tid;
        int k = m * 32 + (idx >> 6);
        int c = c0 + (idx & 63) * 4;
        vh[i] = make_float4(0.f, 0.f, 0.f, 0.f);
        if (c < C)                            // C % 4 == 0 -> all-or-nothing
            vh[i] = w4[((size_t)k * (size_t)C + (size_t)c) >> 2];
    }
}
__device__ __forceinline__ void sts_B(const float4* vh, char* smem, int buf,
                                      int m, int tid) {
    char* base = smem + SM_B + buf * BSZ;
    #pragma unroll
    for (int i = 0; i < 4; i++) {
        int idx = i * 512 + tid;
        int k = m * 32 + (idx >> 6);
        int cq = idx & 63;
        uint2 pk;
        pk.x = pack_bf16x2(vh[i].x, vh[i].y);
        pk.y = pack_bf16x2(vh[i].z, vh[i].w);
        uint32_t byte = (uint32_t)(cq * 8) ^ (uint32_t)(((k >> 3) & 1) << 4);
        *(uint2*)(base + k * BSTRIDE + byte) = pk;
    }
}

// ================= the ONE kernel =================
__global__ void __launch_bounds__(512, 1)
fused_kernel(const float* __restrict__ feat, const float* __restrict__ w,
             const void* __restrict__ target, int C, int NT, int NSLOT,
             float pad, float* __restrict__ out) {
    extern __shared__ char smem[];
    const int tid  = threadIdx.x;
    const int wid  = tid >> 5;
    const int lane = tid & 31;
    const int bid  = blockIdx.x;
    const int wm   = wid >> 2;            // warp row group (32 rows in m-chunk)
    const int wn   = wid & 3;             // warp col group (64 cols)
    const uint32_t sb = smem_u32(smem);

    const int niter = (NT - bid + NCTA - 1) / NCTA;

    // ---- phase 0a: first B tile (fused ldg+sts) ----
    {
        float4 vh[4];
        #pragma unroll
        for (int m = 0; m < 4; m++) {
            ldg_B(vh, w, m, bid * BN, C, tid);
            sts_B(vh, smem, 0, m, tid);
        }
    }
    // ---- phase 0b: A -> fragment-permuted bf16 (distributed; 16 CTAs) ----
    // quad i = mc*2048 + wm*512 + mi*256 + ks*32 + lane   (8192 quads)
    {
        int i = bid * 512 + tid;
        if (i < 8192) {
            int ln = i & 31, ks = (i >> 5) & 7, mi = (i >> 8) & 1;
            int pwm = (i >> 9) & 3, mc = (i >> 11) & 3;
            int r0 = mc * 128 + pwm * 32 + mi * 16 + (ln >> 2);
            int r1 = r0 + 8;
            int kb = ks * 16 + (ln & 3) * 2;
            uint4 q;
            q.x = pack_bf16x2(feat[r0 * FF + kb],     feat[r0 * FF + kb + 1]);
            q.y = pack_bf16x2(feat[r1 * FF + kb],     feat[r1 * FF + kb + 1]);
            q.z = pack_bf16x2(feat[r0 * FF + kb + 8], feat[r0 * FF + kb + 9]);
            q.w = pack_bf16x2(feat[r1 * FF + kb + 8], feat[r1 * FF + kb + 9]);
            g_Apack[i] = q;
        }
    }
    // ---- phase 0c: aux exact-fp32 target-column math (CTAs 0..127) ----
    if (bid < 128 && wid < 4) {
        int b = bid * 4 + wid;
        int t = load_target(target, b, C);
        float fsq = 0.f, wsq = 0.f, dot = 0.f;
        #pragma unroll
        for (int q = 0; q < 4; q++) {
            int f = lane + q * 32;
            float fv = feat[b * FF + f];
            float wv = w[(size_t)f * (size_t)C + (size_t)t];
            fsq = fmaf(fv, fv, fsq);
            wsq = fmaf(wv, wv, wsq);
            dot = fmaf(fv, wv, dot);
        }
        const unsigned msk = 0xffffffffu;
        #pragma unroll
        for (int o = 16; o > 0; o >>= 1) {
            fsq += __shfl_down_sync(msk, fsq, o);
            wsq += __shfl_down_sync(msk, wsq, o);
            dot += __shfl_down_sync(msk, dot, o);
        }
        if (lane == 0) {
            float modulus = sqrtf(fsq) * sqrtf(wsq);
            float ct = dot / (modulus * 1.01f);
            ct = fminf(1.0f, fmaxf(-1.0f, ct));
            float ml = modulus * cosf(acosf(ct) + 0.5f);  // ANGLE=0.5
            g_margin[b] = ml;
            g_adj[b] = expf(ml) - expf(dot);
        }
    }
    gbar_arrive(0);
    gbar_spin(0);          // Apack visible to all; also orders smem B tile

    // B fragment lane base (R5/R10-proven mapping)
    const uint32_t b_lb = (uint32_t)((((lane >> 3) & 1) * 8 + (lane & 7)) * BSTRIDE
                          + (((uint32_t)(wn * 128 + ((lane >> 4) << 4)))
                             ^ (uint32_t)(((lane >> 3) & 1) << 4)));

    const uint4* __restrict__ Ap = g_Apack;

    int cur = 0;
    for (int it = 0; it < niter; it++) {
        const int bx = bid + it * NCTA;
        const bool have_next = (it + 1 < niter);
        const int nc0 = (bx + NCTA) * BN;
        const uint32_t bbase = sb + SM_B + cur * BSZ;

        for (int m = 0; m < 4; m++) {
            float4 vh[4];
            if (have_next)
                ldg_B(vh, w, m, nc0, C, tid);    // LDG early: lands behind MMA

            const int qb = m * 2048 + wm * 512 + lane;

            float acc[2][8][4];
            #pragma unroll
            for (int mi = 0; mi < 2; mi++)
                #pragma unroll
                for (int j = 0; j < 8; j++)
                    #pragma unroll
                    for (int q = 0; q < 4; q++) acc[mi][j][q] = 0.0f;

            #pragma unroll
            for (int ks = 0; ks < 8; ks++) {
                uint4 af0 = Ap[qb + ks * 32];         // mi=0 fragment quad
                uint4 af1 = Ap[qb + 256 + ks * 32];   // mi=1 fragment quad
                #pragma unroll
                for (int np = 0; np < 4; np++) {
                    uint32_t bfr[4];
                    ldsm4t(bfr, bbase + b_lb + ks * 16 * BSTRIDE + np * 32);
                    mma4(acc[0][np * 2 + 0], af0.x, af0.y, af0.z, af0.w, bfr[0], bfr[1]);
                    mma4(acc[0][np * 2 + 1], af0.x, af0.y, af0.z, af0.w, bfr[2], bfr[3]);
                    mma4(acc[1][np * 2 + 0], af1.x, af1.y, af1.z, af1.w, bfr[0], bfr[1]);
                    mma4(acc[1][np * 2 + 1], af1.x, af1.y, af1.z, af1.w, bfr[2], bfr[3]);
                }
            }

            // epilogue: hybrid exp + warp row-sums -> direct STG
            const unsigned msk = 0xffffffffu;
            float* slot = &g_part[(size_t)(bx * 4 + wn) * 512];
            #pragma unroll
            for (int mi = 0; mi < 2; mi++) {
                float s0 = 0.f, s1 = 0.f;
                #pragma unroll
                for (int j = 0; j < 8; j++) {
                    s0 += __expf(acc[mi][j][0]);      // MUFU half
                    s0 += fast_exp(acc[mi][j][1]);    // FMA half
                    s1 += __expf(acc[mi][j][2]);
                    s1 += fast_exp(acc[mi][j][3]);
                }
                s0 += __shfl_xor_sync(msk, s0, 1);
                s0 += __shfl_xor_sync(msk, s0, 2);
                s1 += __shfl_xor_sync(msk, s1, 1);
                s1 += __shfl_xor_sync(msk, s1, 2);
                if ((lane & 3) == 0) {
                    int g = lane >> 2;
                    int grow = m * 128 + wm * 32 + mi * 16 + g;
                    slot[grow]     = s0;
                    slot[grow + 8] = s1;
                }
            }

            if (have_next)
                sts_B(vh, smem, cur ^ 1, m, tid);    // STS late: data long arrived
        }
        __syncthreads();                  // ONE barrier per tile (B swap)
        cur ^= 1;
    }

    // ---- phase 2: finalize1 distributed over all CTAs ----
    gbar_arrive(1);
    gbar_spin(1);                         // g_part fully written

    {
        float* red = (float*)smem;        // reuse smem (post-barrier)
        int rl = tid >> 7;                // row slot 0..3
        int j  = tid & 127;
        int row = bid + rl * NCTA;        // rows bid, bid+148, +296, +444
        float s = 0.f;
        if (row < BB)
            for (int t = j; t < NSLOT; t += 128)   // fixed order: deterministic
                s += g_part[(size_t)t * 512 + row];
        red[rl * 128 + j] = s;
        __syncthreads();
        #pragma unroll
        for (int o = 64; o > 0; o >>= 1) {
            if (j < o) red[rl * 128 + j] += red[rl * 128 + j + o];
            __syncthreads();
        }
        if (j == 0 && row < BB) {
            float down = red[rl * 128] - pad + g_adj[row];
            g_rowv[row] = logf(down) - g_margin[row];
        }
    }

    // ---- phase 3: CTA 0 reduces 512 row values, writes out, resets ----
    gbar_arrive(2);                       // all CTAs arrive; non-0 CTAs exit
    if (bid != 0) return;
    gbar_spin(2);                         // only CTA 0 spins

    {
        float* red = (float*)smem;
        red[tid] = g_rowv[tid];           // 512 rows, 512 threads
        __syncthreads();
        #pragma unroll
        for (int o = 256; o > 0; o >>= 1) {
            if (tid < o) red[tid] += red[tid + o];
            __syncthreads();
        }
        if (tid == 0) {
            out[0] = red[0] / (float)BB;
            // reset barrier counters for the next graph replay (everyone else
            // has arrived at g_cnt[2] and exited; no one reads these again)
            g_cnt[0] = 0; g_cnt[1] = 0; g_cnt[2] = 0;
            __threadfence();
        }
    }
}

// ================= launch =================
extern "C" void kernel_launch(void* const* d_in, const int* in_sizes, int n_in,
                              void* d_out, int out_size) {
    const float* feat = (const float*)d_in[0];
    const float* w    = (const float*)d_in[1];
    const void*  target = d_in[2];
    float* out = (float*)d_out;

    int C  = in_sizes[1] / FF;               // 100000
    int NT = (C + BN - 1) / BN;              // 391
    float pad = (float)(NT * BN - C);        // 96

    cudaFuncSetAttribute(fused_kernel,
                         cudaFuncAttributeMaxDynamicSharedMemorySize, SM_TOTAL);

    fused_kernel<<<NCTA, 512, SM_TOTAL>>>(feat, w, target, C, NT, 4 * NT,
                                          pad, out);
}

// round 15
// speedup vs baseline: 1.1940x; 1.0998x over previous
#include <cuda_runtime.h>
#include <cuda_bf16.h>
#include <math.h>
#include <stdint.h>

// ArcFace loss. B=512, F=128, C=100000.
// R10 structure (best 65.6us), occupancy change only: 2 CTAs/SM x 256 thr,
// BN=128 (NT=782). Cross-CTA overlap hides barrier/LDSM latency; half-size
// tiles + early-exit CTAs shrink the tail imbalance.

#define FF 128
#define BB 512
#define BN 128
#define NCTA 296

__device__ float g_part[1600 * 512];  // [slot = bx*2 + wn][row]
__device__ float g_margin[BB];
__device__ float g_adj[BB];
__device__ float g_rowv[BB];
__device__ uint4 g_Apack[8192];       // permuted bf16 A fragments (128KB)

// smem: B 2 x (128 k-rows x 272B)   ([k][n] bf16, n=128 -> 256B + 16B pad)
#define BSTRIDE 272
#define BSZ     (128 * BSTRIDE)      // 34816
#define SM_B    0
#define SM_TOTAL (2 * BSZ)           // 69632 per CTA (2 CTAs -> 136KB/SM)

__device__ __forceinline__ uint32_t smem_u32(const void* p) {
    uint32_t a;
    asm("{ .reg .u64 t; cvta.to.shared.u64 t, %1; cvt.u32.u64 %0, t; }"
        : "=r"(a) : "l"(p));
    return a;
}
__device__ __forceinline__ void ldsm4t(uint32_t* r, uint32_t addr) {
    asm volatile("ldmatrix.sync.aligned.m8n8.x4.trans.shared.b16 {%0,%1,%2,%3}, [%4];"
                 : "=r"(r[0]), "=r"(r[1]), "=r"(r[2]), "=r"(r[3]) : "r"(addr));
}
__device__ __forceinline__ void mma4(float* d, uint32_t a0, uint32_t a1,
                                     uint32_t a2, uint32_t a3,
                                     uint32_t b0, uint32_t b1) {
    asm volatile(
        "mma.sync.aligned.m16n8k16.row.col.f32.bf16.bf16.f32 "
        "{%0,%1,%2,%3}, {%4,%5,%6,%7}, {%8,%9}, {%0,%1,%2,%3};"
        : "+f"(d[0]), "+f"(d[1]), "+f"(d[2]), "+f"(d[3])
        : "r"(a0), "r"(a1), "r"(a2), "r"(a3), "r"(b0), "r"(b1));
}
__device__ __forceinline__ uint32_t pack_bf16x2(float lo, float hi) {
    __nv_bfloat162 p = __floats2bfloat162_rn(lo, hi);
    return *(uint32_t*)&p;
}
// FMA-pipe exp (deg-6, exact at 0).
__device__ __forceinline__ float fast_exp(float x) {
    float z = x * 1.4426950408889634f;
    float n = rintf(z);
    float f = z - n;
    float p = 1.5403530393381606e-4f;
    p = fmaf(p, f, 1.3333558146428443e-3f);
    p = fmaf(p, f, 9.6181291076284770e-3f);
    p = fmaf(p, f, 5.5504108664821580e-2f);
    p = fmaf(p, f, 2.4022650695910070e-1f);
    p = fmaf(p, f, 6.9314718055994530e-1f);
    p = fmaf(p, f, 1.0f);
    return __int_as_float(__float_as_int(p) + ((int)n << 23));
}
__device__ __forceinline__ int load_target(const void* tptr, int b, int C) {
    const int* p = (const int*)tptr;
    bool is64 = ((p[1] | p[3] | p[5] | p[7] | p[9]) == 0);
    long long t = is64 ? ((const long long*)tptr)[b] : (long long)p[b];
    if (t < 0) t = 0;
    if (t >= C) t = C - 1;
    return (int)t;
}

// ======== pre-kernel: A -> fragment-permuted bf16 (R10-proven) ========
// quad i = mc*2048 + wm*512 + mi*256 + ks*32 + lane   (8192 quads)
__global__ void precvt_A(const float* __restrict__ feat) {
    int i = blockIdx.x * 256 + threadIdx.x;     // 0..8191
    int lane = i & 31, ks = (i >> 5) & 7, mi = (i >> 8) & 1;
    int wm = (i >> 9) & 3, mc = (i >> 11) & 3;
    int r0 = mc * 128 + wm * 32 + mi * 16 + (lane >> 2);
    int r1 = r0 + 8;
    int kb = ks * 16 + (lane & 3) * 2;
    uint4 q;
    q.x = pack_bf16x2(feat[r0 * FF + kb],     feat[r0 * FF + kb + 1]);
    q.y = pack_bf16x2(feat[r1 * FF + kb],     feat[r1 * FF + kb + 1]);
    q.z = pack_bf16x2(feat[r0 * FF + kb + 8], feat[r0 * FF + kb + 9]);
    q.w = pack_bf16x2(feat[r1 * FF + kb + 8], feat[r1 * FF + kb + 9]);
    g_Apack[i] = q;
}

// ======== B chunk (32 k-rows x 128 n): LDG / cvt+STS split ========
__device__ __forceinline__ void ldg_B(float4* vh, const float* __restrict__ w,
                                      int m, int c0, int C, int tid) {
    const float4* w4 = (const float4*)w;
    #pragma unroll
    for (int i = 0; i < 4; i++) {
        int idx = i * 256 + tid;              // 0..1023
        int k = m * 32 + (idx >> 5);
        int c = c0 + (idx & 31) * 4;
        vh[i] = make_float4(0.f, 0.f, 0.f, 0.f);
        if (c < C)                            // C % 4 == 0 -> all-or-nothing
            vh[i] = w4[((size_t)k * (size_t)C + (size_t)c) >> 2];
    }
}
__device__ __forceinline__ void sts_B(const float4* vh, char* smem, int buf,
                                      int m, int tid) {
    char* base = smem + SM_B + buf * BSZ;
    #pragma unroll
    for (int i = 0; i < 4; i++) {
        int idx = i * 256 + tid;
        int k = m * 32 + (idx >> 5);
        int cq = idx & 31;
        uint2 pk;
        pk.x = pack_bf16x2(vh[i].x, vh[i].y);
        pk.y = pack_bf16x2(vh[i].z, vh[i].w);
        uint32_t byte = (uint32_t)(cq * 8) ^ (uint32_t)(((k >> 3) & 1) << 4);
        *(uint2*)(base + k * BSTRIDE + byte) = pk;
    }
}

// ================= persistent fused kernel (2 CTAs/SM) =================
__global__ void __launch_bounds__(256, 2)
fused_kernel(const float* __restrict__ feat, const float* __restrict__ w,
             const void* __restrict__ target, int C, int NT) {
    extern __shared__ char smem[];
    const int tid  = threadIdx.x;
    const int wid  = tid >> 5;            // 0..7
    const int lane = tid & 31;
    const int bid  = blockIdx.x;
    const int wm   = wid >> 1;            // warp row group 0..3 (32 rows)
    const int wn   = wid & 1;             // warp col group 0..1 (64 cols)
    const uint32_t sb = smem_u32(smem);

    const int niter = (NT - bid + NCTA - 1) / NCTA;

    // ---- prologue: first B tile (fused ldg+sts) ----
    {
        float4 vh[4];
        #pragma unroll
        for (int m = 0; m < 4; m++) {
            ldg_B(vh, w, m, bid * BN, C, tid);
            sts_B(vh, smem, 0, m, tid);
        }
    }
    // aux: exact-fp32 target-column math (CTAs 0..127, 4 warps each)
    if (bid < 128 && wid < 4) {
        int b = bid * 4 + wid;
        int t = load_target(target, b, C);
        float fsq = 0.f, wsq = 0.f, dot = 0.f;
        #pragma unroll
        for (int q = 0; q < 4; q++) {
            int f = lane + q * 32;
            float fv = feat[b * FF + f];
            float wv = w[(size_t)f * (size_t)C + (size_t)t];
            fsq = fmaf(fv, fv, fsq);
            wsq = fmaf(wv, wv, wsq);
            dot = fmaf(fv, wv, dot);
        }
        const unsigned msk = 0xffffffffu;
        #pragma unroll
        for (int o = 16; o > 0; o >>= 1) {
            fsq += __shfl_down_sync(msk, fsq, o);
            wsq += __shfl_down_sync(msk, wsq, o);
            dot += __shfl_down_sync(msk, dot, o);
        }
        if (lane == 0) {
            float modulus = sqrtf(fsq) * sqrtf(wsq);
            float ct = dot / (modulus * 1.01f);
            ct = fminf(1.0f, fmaxf(-1.0f, ct));
            float ml = modulus * cosf(acosf(ct) + 0.5f);  // ANGLE=0.5
            g_margin[b] = ml;
            g_adj[b] = expf(ml) - expf(dot);
        }
    }
    __syncthreads();

    // B fragment lane base (R5/R10-proven mapping, BSTRIDE=272, wn in {0,1})
    const uint32_t b_lb = (uint32_t)((((lane >> 3) & 1) * 8 + (lane & 7)) * BSTRIDE
                          + (((uint32_t)(wn * 128 + ((lane >> 4) << 4)))
                             ^ (uint32_t)(((lane >> 3) & 1) << 4)));

    const uint4* __restrict__ Ap = g_Apack;

    int cur = 0;
    for (int it = 0; it < niter; it++) {
        const int bx = bid + it * NCTA;
        const bool have_next = (it + 1 < niter);
        const int nc0 = (bx + NCTA) * BN;
        const uint32_t bbase = sb + SM_B + cur * BSZ;

        for (int m = 0; m < 4; m++) {
            float4 vh[4];
            if (have_next)
                ldg_B(vh, w, m, nc0, C, tid);    // LDG early: lands behind MMA

            const int qb = m * 2048 + wm * 512 + lane;

            float acc[2][8][4];
            #pragma unroll
            for (int mi = 0; mi < 2; mi++)
                #pragma unroll
                for (int j = 0; j < 8; j++)
                    #pragma unroll
                    for (int q = 0; q < 4; q++) acc[mi][j][q] = 0.0f;

            #pragma unroll
            for (int ks = 0; ks < 8; ks++) {
                uint4 af0 = Ap[qb + ks * 32];         // mi=0 fragment quad
                uint4 af1 = Ap[qb + 256 + ks * 32];   // mi=1 fragment quad
                #pragma unroll
                for (int np = 0; np < 4; np++) {
                    uint32_t bfr[4];
                    ldsm4t(bfr, bbase + b_lb + ks * 16 * BSTRIDE + np * 32);
                    mma4(acc[0][np * 2 + 0], af0.x, af0.y, af0.z, af0.w, bfr[0], bfr[1]);
                    mma4(acc[0][np * 2 + 1], af0.x, af0.y, af0.z, af0.w, bfr[2], bfr[3]);
                    mma4(acc[1][np * 2 + 0], af1.x, af1.y, af1.z, af1.w, bfr[0], bfr[1]);
                    mma4(acc[1][np * 2 + 1], af1.x, af1.y, af1.z, af1.w, bfr[2], bfr[3]);
                }
            }

            // epilogue: hybrid exp + warp row-sums -> direct STG
            const unsigned msk = 0xffffffffu;
            float* slot = &g_part[(size_t)(bx * 2 + wn) * 512];
            #pragma unroll
            for (int mi = 0; mi < 2; mi++) {
                float s0 = 0.f, s1 = 0.f;
                #pragma unroll
                for (int j = 0; j < 8; j++) {
                    s0 += __expf(acc[mi][j][0]);      // MUFU half
                    s0 += fast_exp(acc[mi][j][1]);    // FMA half
                    s1 += __expf(acc[mi][j][2]);
                    s1 += fast_exp(acc[mi][j][3]);
                }
                s0 += __shfl_xor_sync(msk, s0, 1);
                s0 += __shfl_xor_sync(msk, s0, 2);
                s1 += __shfl_xor_sync(msk, s1, 1);
                s1 += __shfl_xor_sync(msk, s1, 2);
                if ((lane & 3) == 0) {
                    int g = lane >> 2;
                    int grow = m * 128 + wm * 32 + mi * 16 + g;
                    slot[grow]     = s0;
                    slot[grow + 8] = s1;
                }
            }

            if (have_next)
                sts_B(vh, smem, cur ^ 1, m, tid);    // STS late: data long arrived
        }
        __syncthreads();                  // ONE barrier per tile (B swap)
        cur ^= 1;
    }
}

// ================= finalize 1: per-row value =================
__global__ void finalize1_kernel(int NSLOT, float pad) {
    int row = blockIdx.x;        // 0..511
    int j = threadIdx.x;         // 0..127
    float s = 0.f;
    for (int t = j; t < NSLOT; t += 128)      // fixed order -> deterministic
        s += g_part[(size_t)t * 512 + row];
    __shared__ float red[128];
    red[j] = s;
    __syncthreads();
    #pragma unroll
    for (int o = 64; o > 0; o >>= 1) {
        if (j < o) red[j] += red[j + o];
        __syncthreads();
    }
    if (j == 0) {
        float down = red[0] - pad + g_adj[row];
        g_rowv[row] = logf(down) - g_margin[row];
    }
}

// ================= finalize 2: scalar =================
__global__ void finalize2_kernel(float* __restrict__ out) {
    int b = threadIdx.x;         // 0..511
    __shared__ float red[BB];
    red[b] = g_rowv[b];
    __syncthreads();
    #pragma unroll
    for (int o = BB / 2; o > 0; o >>= 1) {
        if (b < o) red[b] += red[b + o];
        __syncthreads();
    }
    if (b == 0) out[0] = red[0] / (float)BB;
}

// ================= launch =================
extern "C" void kernel_launch(void* const* d_in, const int* in_sizes, int n_in,
                              void* d_out, int out_size) {
    const float* feat = (const float*)d_in[0];
    const float* w    = (const float*)d_in[1];
    const void*  target = d_in[2];
    float* out = (float*)d_out;

    int C  = in_sizes[1] / FF;               // 100000
    int NT = (C + BN - 1) / BN;              // 782
    float pad = (float)(NT * BN - C);        // 96

    cudaFuncSetAttribute(fused_kernel,
                         cudaFuncAttributeMaxDynamicSharedMemorySize, SM_TOTAL);

    precvt_A<<<32, 256>>>(feat);
    fused_kernel<<<NCTA, 256, SM_TOTAL>>>(feat, w, target, C, NT);
    finalize1_kernel<<<BB, 128>>>(2 * NT, pad);
    finalize2_kernel<<<1, BB>>>(out);
}

// round 16
// speedup vs baseline: 1.2393x; 1.0379x over previous
#include <cuda_runtime.h>
#include <cuda_bf16.h>
#include <math.h>
#include <stdint.h>

// ArcFace loss. B=512, F=128, C=100000.
// R15 core (best 62.2us: 2 CTAs/SM x 256thr, BN=128, A-frag LDG, B dbuf).
// R16: exp split rebalanced to 75% MUFU / 25% FMA-poly (FMA pipe was the
// epilogue co-bottleneck), finalize1+2 merged via last-block-done pattern.

#define FF 128
#define BB 512
#define BN 128
#define NCTA 296

__device__ float g_part[1600 * 512];  // [slot = bx*2 + wn][row]
__device__ float g_margin[BB];
__device__ float g_adj[BB];
__device__ float g_rowv[BB];
__device__ uint4 g_Apack[8192];       // permuted bf16 A fragments (128KB)
__device__ unsigned g_fincnt;         // finalize completion counter (zero-init)

// smem: B 2 x (128 k-rows x 272B)
#define BSTRIDE 272
#define BSZ     (128 * BSTRIDE)      // 34816
#define SM_B    0
#define SM_TOTAL (2 * BSZ)           // 69632 per CTA (2 CTAs -> 136KB/SM)

__device__ __forceinline__ uint32_t smem_u32(const void* p) {
    uint32_t a;
    asm("{ .reg .u64 t; cvta.to.shared.u64 t, %1; cvt.u32.u64 %0, t; }"
        : "=r"(a) : "l"(p));
    return a;
}
__device__ __forceinline__ void ldsm4t(uint32_t* r, uint32_t addr) {
    asm volatile("ldmatrix.sync.aligned.m8n8.x4.trans.shared.b16 {%0,%1,%2,%3}, [%4];"
                 : "=r"(r[0]), "=r"(r[1]), "=r"(r[2]), "=r"(r[3]) : "r"(addr));
}
__device__ __forceinline__ void mma4(float* d, uint32_t a0, uint32_t a1,
                                     uint32_t a2, uint32_t a3,
                                     uint32_t b0, uint32_t b1) {
    asm volatile(
        "mma.sync.aligned.m16n8k16.row.col.f32.bf16.bf16.f32 "
        "{%0,%1,%2,%3}, {%4,%5,%6,%7}, {%8,%9}, {%0,%1,%2,%3};"
        : "+f"(d[0]), "+f"(d[1]), "+f"(d[2]), "+f"(d[3])
        : "r"(a0), "r"(a1), "r"(a2), "r"(a3), "r"(b0), "r"(b1));
}
__device__ __forceinline__ uint32_t pack_bf16x2(float lo, float hi) {
    __nv_bfloat162 p = __floats2bfloat162_rn(lo, hi);
    return *(uint32_t*)&p;
}
// FMA-pipe exp (deg-6, exact at 0).
__device__ __forceinline__ float fast_exp(float x) {
    float z = x * 1.4426950408889634f;
    float n = rintf(z);
    float f = z - n;
    float p = 1.5403530393381606e-4f;
    p = fmaf(p, f, 1.3333558146428443e-3f);
    p = fmaf(p, f, 9.6181291076284770e-3f);
    p = fmaf(p, f, 5.5504108664821580e-2f);
    p = fmaf(p, f, 2.4022650695910070e-1f);
    p = fmaf(p, f, 6.9314718055994530e-1f);
    p = fmaf(p, f, 1.0f);
    return __int_as_float(__float_as_int(p) + ((int)n << 23));
}
__device__ __forceinline__ int load_target(const void* tptr, int b, int C) {
    const int* p = (const int*)tptr;
    bool is64 = ((p[1] | p[3] | p[5] | p[7] | p[9]) == 0);
    long long t = is64 ? ((const long long*)tptr)[b] : (long long)p[b];
    if (t < 0) t = 0;
    if (t >= C) t = C - 1;
    return (int)t;
}

// ======== pre-kernel: A -> fragment-permuted bf16 (R10-proven) ========
__global__ void precvt_A(const float* __restrict__ feat) {
    int i = blockIdx.x * 256 + threadIdx.x;     // 0..8191
    int lane = i & 31, ks = (i >> 5) & 7, mi = (i >> 8) & 1;
    int wm = (i >> 9) & 3, mc = (i >> 11) & 3;
    int r0 = mc * 128 + wm * 32 + mi * 16 + (lane >> 2);
    int r1 = r0 + 8;
    int kb = ks * 16 + (lane & 3) * 2;
    uint4 q;
    q.x = pack_bf16x2(feat[r0 * FF + kb],     feat[r0 * FF + kb + 1]);
    q.y = pack_bf16x2(feat[r1 * FF + kb],     feat[r1 * FF + kb + 1]);
    q.z = pack_bf16x2(feat[r0 * FF + kb + 8], feat[r0 * FF + kb + 9]);
    q.w = pack_bf16x2(feat[r1 * FF + kb + 8], feat[r1 * FF + kb + 9]);
    g_Apack[i] = q;
}

// ======== B chunk (32 k-rows x 128 n): LDG / cvt+STS split ========
__device__ __forceinline__ void ldg_B(float4* vh, const float* __restrict__ w,
                                      int m, int c0, int C, int tid) {
    const float4* w4 = (const float4*)w;
    #pragma unroll
    for (int i = 0; i < 4; i++) {
        int idx = i * 256 + tid;              // 0..1023
        int k = m * 32 + (idx >> 5);
        int c = c0 + (idx & 31) * 4;
        vh[i] = make_float4(0.f, 0.f, 0.f, 0.f);
        if (c < C)                            // C % 4 == 0 -> all-or-nothing
            vh[i] = w4[((size_t)k * (size_t)C + (size_t)c) >> 2];
    }
}
__device__ __forceinline__ void sts_B(const float4* vh, char* smem, int buf,
                                      int m, int tid) {
    char* base = smem + SM_B + buf * BSZ;
    #pragma unroll
    for (int i = 0; i < 4; i++) {
        int idx = i * 256 + tid;
        int k = m * 32 + (idx >> 5);
        int cq = idx & 31;
        uint2 pk;
        pk.x = pack_bf16x2(vh[i].x, vh[i].y);
        pk.y = pack_bf16x2(vh[i].z, vh[i].w);
        uint32_t byte = (uint32_t)(cq * 8) ^ (uint32_t)(((k >> 3) & 1) << 4);
        *(uint2*)(base + k * BSTRIDE + byte) = pk;
    }
}

// ================= persistent fused kernel (2 CTAs/SM) =================
__global__ void __launch_bounds__(256, 2)
fused_kernel(const float* __restrict__ feat, const float* __restrict__ w,
             const void* __restrict__ target, int C, int NT) {
    extern __shared__ char smem[];
    const int tid  = threadIdx.x;
    const int wid  = tid >> 5;            // 0..7
    const int lane = tid & 31;
    const int bid  = blockIdx.x;
    const int wm   = wid >> 1;            // warp row group 0..3 (32 rows)
    const int wn   = wid & 1;             // warp col group 0..1 (64 cols)
    const uint32_t sb = smem_u32(smem);

    const int niter = (NT - bid + NCTA - 1) / NCTA;

    // ---- prologue: first B tile (fused ldg+sts) ----
    {
        float4 vh[4];
        #pragma unroll
        for (int m = 0; m < 4; m++) {
            ldg_B(vh, w, m, bid * BN, C, tid);
            sts_B(vh, smem, 0, m, tid);
        }
    }
    // aux: exact-fp32 target-column math (CTAs 0..127, 4 warps each)
    if (bid < 128 && wid < 4) {
        int b = bid * 4 + wid;
        int t = load_target(target, b, C);
        float fsq = 0.f, wsq = 0.f, dot = 0.f;
        #pragma unroll
        for (int q = 0; q < 4; q++) {
            int f = lane + q * 32;
            float fv = feat[b * FF + f];
            float wv = w[(size_t)f * (size_t)C + (size_t)t];
            fsq = fmaf(fv, fv, fsq);
            wsq = fmaf(wv, wv, wsq);
            dot = fmaf(fv, wv, dot);
        }
        const unsigned msk = 0xffffffffu;
        #pragma unroll
        for (int o = 16; o > 0; o >>= 1) {
            fsq += __shfl_down_sync(msk, fsq, o);
            wsq += __shfl_down_sync(msk, wsq, o);
            dot += __shfl_down_sync(msk, dot, o);
        }
        if (lane == 0) {
            float modulus = sqrtf(fsq) * sqrtf(wsq);
            float ct = dot / (modulus * 1.01f);
            ct = fminf(1.0f, fmaxf(-1.0f, ct));
            float ml = modulus * cosf(acosf(ct) + 0.5f);  // ANGLE=0.5
            g_margin[b] = ml;
            g_adj[b] = expf(ml) - expf(dot);
        }
    }
    __syncthreads();

    // B fragment lane base (proven mapping, BSTRIDE=272, wn in {0,1})
    const uint32_t b_lb = (uint32_t)((((lane >> 3) & 1) * 8 + (lane & 7)) * BSTRIDE
                          + (((uint32_t)(wn * 128 + ((lane >> 4) << 4)))
                             ^ (uint32_t)(((lane >> 3) & 1) << 4)));

    const uint4* __restrict__ Ap = g_Apack;

    int cur = 0;
    for (int it = 0; it < niter; it++) {
        const int bx = bid + it * NCTA;
        const bool have_next = (it + 1 < niter);
        const int nc0 = (bx + NCTA) * BN;
        const uint32_t bbase = sb + SM_B + cur * BSZ;

        for (int m = 0; m < 4; m++) {
            float4 vh[4];
            if (have_next)
                ldg_B(vh, w, m, nc0, C, tid);    // LDG early: lands behind MMA

            const int qb = m * 2048 + wm * 512 + lane;

            float acc[2][8][4];
            #pragma unroll
            for (int mi = 0; mi < 2; mi++)
                #pragma unroll
                for (int j = 0; j < 8; j++)
                    #pragma unroll
                    for (int q = 0; q < 4; q++) acc[mi][j][q] = 0.0f;

            #pragma unroll
            for (int ks = 0; ks < 8; ks++) {
                uint4 af0 = Ap[qb + ks * 32];         // mi=0 fragment quad
                uint4 af1 = Ap[qb + 256 + ks * 32];   // mi=1 fragment quad
                #pragma unroll
                for (int np = 0; np < 4; np++) {
                    uint32_t bfr[4];
                    ldsm4t(bfr, bbase + b_lb + ks * 16 * BSTRIDE + np * 32);
                    mma4(acc[0][np * 2 + 0], af0.x, af0.y, af0.z, af0.w, bfr[0], bfr[1]);
                    mma4(acc[0][np * 2 + 1], af0.x, af0.y, af0.z, af0.w, bfr[2], bfr[3]);
                    mma4(acc[1][np * 2 + 0], af1.x, af1.y, af1.z, af1.w, bfr[0], bfr[1]);
                    mma4(acc[1][np * 2 + 1], af1.x, af1.y, af1.z, af1.w, bfr[2], bfr[3]);
                }
            }

            // epilogue: exp 75% MUFU / 25% FMA-poly + warp row-sums -> STG
            const unsigned msk = 0xffffffffu;
            float* slot = &g_part[(size_t)(bx * 2 + wn) * 512];
            #pragma unroll
            for (int mi = 0; mi < 2; mi++) {
                float s0 = 0.f, s1 = 0.f;
                #pragma unroll
                for (int j = 0; j < 8; j++) {
                    s0 += __expf(acc[mi][j][0]);      // MUFU
                    s0 += __expf(acc[mi][j][1]);      // MUFU
                    s1 += __expf(acc[mi][j][2]);      // MUFU
                    s1 += fast_exp(acc[mi][j][3]);    // FMA poly (25%)
                }
                s0 += __shfl_xor_sync(msk, s0, 1);
                s0 += __shfl_xor_sync(msk, s0, 2);
                s1 += __shfl_xor_sync(msk, s1, 1);
                s1 += __shfl_xor_sync(msk, s1, 2);
                if ((lane & 3) == 0) {
                    int g = lane >> 2;
                    int grow = m * 128 + wm * 32 + mi * 16 + g;
                    slot[grow]     = s0;
                    slot[grow + 8] = s1;
                }
            }

            if (have_next)
                sts_B(vh, smem, cur ^ 1, m, tid);    // STS late: data long arrived
        }
        __syncthreads();                  // ONE barrier per tile (B swap)
        cur ^= 1;
    }
}

// ================= finalize (merged): per-row value + last-block scalar ====
__global__ void finalize_kernel(int NSLOT, float pad, float* __restrict__ out) {
    int row = blockIdx.x;        // 0..511
    int j = threadIdx.x;         // 0..127
    float s = 0.f;
    for (int t = j; t < NSLOT; t += 128)      // fixed order -> deterministic
        s += g_part[(size_t)t * 512 + row];
    __shared__ float red[128];
    __shared__ bool last;
    red[j] = s;
    __syncthreads();
    #pragma unroll
    for (int o = 64; o > 0; o >>= 1) {
        if (j < o) red[j] += red[j + o];
        __syncthreads();
    }
    if (j == 0) {
        float down = red[0] - pad + g_adj[row];
        g_rowv[row] = logf(down) - g_margin[row];
        __threadfence();                          // release g_rowv[row]
        unsigned t = atomicAdd(&g_fincnt, 1u);
        last = (t == (unsigned)(BB - 1));
    }
    __syncthreads();
    if (!last) return;
    __threadfence();                              // acquire all g_rowv

    // the last-arriving block does the fixed-order 512-sum (order-independent
    // of WHICH block runs it -> deterministic)
    float v = (g_rowv[j] + g_rowv[j + 128]) + (g_rowv[j + 256] + g_rowv[j + 384]);
    red[j] = v;
    __syncthreads();
    #pragma unroll
    for (int o = 64; o > 0; o >>= 1) {
        if (j < o) red[j] += red[j + o];
        __syncthreads();
    }
    if (j == 0) {
        out[0] = red[0] / (float)BB;
        g_fincnt = 0;                             // reset for graph replay
        __threadfence();
    }
}

// ================= launch =================
extern "C" void kernel_launch(void* const* d_in, const int* in_sizes, int n_in,
                              void* d_out, int out_size) {
    const float* feat = (const float*)d_in[0];
    const float* w    = (const float*)d_in[1];
    const void*  target = d_in[2];
    float* out = (float*)d_out;

    int C  = in_sizes[1] / FF;               // 100000
    int NT = (C + BN - 1) / BN;              // 782
    float pad = (float)(NT * BN - C);        // 96

    cudaFuncSetAttribute(fused_kernel,
                         cudaFuncAttributeMaxDynamicSharedMemorySize, SM_TOTAL);

    precvt_A<<<32, 256>>>(feat);
    fused_kernel<<<NCTA, 256, SM_TOTAL>>>(feat, w, target, C, NT);
    finalize_kernel<<<BB, 128>>>(2 * NT, pad, out);
}

// round 17
// speedup vs baseline: 1.2460x; 1.0054x over previous
#include <cuda_runtime.h>
#include <cuda_bf16.h>
#include <math.h>
#include <stdint.h>

// ArcFace loss. B=512, F=128, C=100000.
// R16 core (59.9us) + precvt folded into fused kernel behind a start-of-kernel
// grid barrier (kills one launch) + exp split 87.5% MUFU / 12.5% FMA-poly.

#define FF 128
#define BB 512
#define BN 128
#define NCTA 296

__device__ float g_part[1600 * 512];  // [slot = bx*2 + wn][row]
__device__ float g_margin[BB];
__device__ float g_adj[BB];
__device__ float g_rowv[BB];
__device__ uint4 g_Apack[8192];       // permuted bf16 A fragments (128KB)
__device__ unsigned g_fincnt;         // finalize completion counter (zero-init)
__device__ volatile unsigned g_cnt0;  // start barrier counter (zero-init)

// smem: B 2 x (128 k-rows x 272B)
#define BSTRIDE 272
#define BSZ     (128 * BSTRIDE)      // 34816
#define SM_B    0
#define SM_TOTAL (2 * BSZ)           // 69632 per CTA (2 CTAs -> 136KB/SM)

__device__ __forceinline__ uint32_t smem_u32(const void* p) {
    uint32_t a;
    asm("{ .reg .u64 t; cvta.to.shared.u64 t, %1; cvt.u32.u64 %0, t; }"
        : "=r"(a) : "l"(p));
    return a;
}
__device__ __forceinline__ void ldsm4t(uint32_t* r, uint32_t addr) {
    asm volatile("ldmatrix.sync.aligned.m8n8.x4.trans.shared.b16 {%0,%1,%2,%3}, [%4];"
                 : "=r"(r[0]), "=r"(r[1]), "=r"(r[2]), "=r"(r[3]) : "r"(addr));
}
__device__ __forceinline__ void mma4(float* d, uint32_t a0, uint32_t a1,
                                     uint32_t a2, uint32_t a3,
                                     uint32_t b0, uint32_t b1) {
    asm volatile(
        "mma.sync.aligned.m16n8k16.row.col.f32.bf16.bf16.f32 "
        "{%0,%1,%2,%3}, {%4,%5,%6,%7}, {%8,%9}, {%0,%1,%2,%3};"
        : "+f"(d[0]), "+f"(d[1]), "+f"(d[2]), "+f"(d[3])
        : "r"(a0), "r"(a1), "r"(a2), "r"(a3), "r"(b0), "r"(b1));
}
__device__ __forceinline__ uint32_t pack_bf16x2(float lo, float hi) {
    __nv_bfloat162 p = __floats2bfloat162_rn(lo, hi);
    return *(uint32_t*)&p;
}
// FMA-pipe exp (deg-6, exact at 0).
__device__ __forceinline__ float fast_exp(float x) {
    float z = x * 1.4426950408889634f;
    float n = rintf(z);
    float f = z - n;
    float p = 1.5403530393381606e-4f;
    p = fmaf(p, f, 1.3333558146428443e-3f);
    p = fmaf(p, f, 9.6181291076284770e-3f);
    p = fmaf(p, f, 5.5504108664821580e-2f);
    p = fmaf(p, f, 2.4022650695910070e-1f);
    p = fmaf(p, f, 6.9314718055994530e-1f);
    p = fmaf(p, f, 1.0f);
    return __int_as_float(__float_as_int(p) + ((int)n << 23));
}
__device__ __forceinline__ int load_target(const void* tptr, int b, int C) {
    const int* p = (const int*)tptr;
    bool is64 = ((p[1] | p[3] | p[5] | p[7] | p[9]) == 0);
    long long t = is64 ? ((const long long*)tptr)[b] : (long long)p[b];
    if (t < 0) t = 0;
    if (t >= C) t = C - 1;
    return (int)t;
}

// ======== B chunk (32 k-rows x 128 n): LDG / cvt+STS split ========
__device__ __forceinline__ void ldg_B(float4* vh, const float* __restrict__ w,
                                      int m, int c0, int C, int tid) {
    const float4* w4 = (const float4*)w;
    #pragma unroll
    for (int i = 0; i < 4; i++) {
        int idx = i * 256 + tid;              // 0..1023
        int k = m * 32 + (idx >> 5);
        int c = c0 + (idx & 31) * 4;
        vh[i] = make_float4(0.f, 0.f, 0.f, 0.f);
        if (c < C)                            // C % 4 == 0 -> all-or-nothing
            vh[i] = w4[((size_t)k * (size_t)C + (size_t)c) >> 2];
    }
}
__device__ __forceinline__ void sts_B(const float4* vh, char* smem, int buf,
                                      int m, int tid) {
    char* base = smem + SM_B + buf * BSZ;
    #pragma unroll
    for (int i = 0; i < 4; i++) {
        int idx = i * 256 + tid;
        int k = m * 32 + (idx >> 5);
        int cq = idx & 31;
        uint2 pk;
        pk.x = pack_bf16x2(vh[i].x, vh[i].y);
        pk.y = pack_bf16x2(vh[i].z, vh[i].w);
        uint32_t byte = (uint32_t)(cq * 8) ^ (uint32_t)(((k >> 3) & 1) << 4);
        *(uint2*)(base + k * BSTRIDE + byte) = pk;
    }
}

// ================= persistent fused kernel (2 CTAs/SM) =================
__global__ void __launch_bounds__(256, 2)
fused_kernel(const float* __restrict__ feat, const float* __restrict__ w,
             const void* __restrict__ target, int C, int NT) {
    extern __shared__ char smem[];
    const int tid  = threadIdx.x;
    const int wid  = tid >> 5;            // 0..7
    const int lane = tid & 31;
    const int bid  = blockIdx.x;
    const int wm   = wid >> 1;            // warp row group 0..3 (32 rows)
    const int wn   = wid & 1;             // warp col group 0..1 (64 cols)
    const uint32_t sb = smem_u32(smem);

    const int niter = (NT - bid + NCTA - 1) / NCTA;

    // ---- prologue: first B tile (fused ldg+sts) ----
    {
        float4 vh[4];
        #pragma unroll
        for (int m = 0; m < 4; m++) {
            ldg_B(vh, w, m, bid * BN, C, tid);
            sts_B(vh, smem, 0, m, tid);
        }
    }
    // ---- A -> fragment-permuted bf16 (CTAs 0..31, one quad per thread) ----
    // quad i = mc*2048 + wm*512 + mi*256 + ks*32 + lane   (8192 quads)
    {
        int i = bid * 256 + tid;
        if (i < 8192) {
            int ln = i & 31, ks = (i >> 5) & 7, mi = (i >> 8) & 1;
            int pwm = (i >> 9) & 3, mc = (i >> 11) & 3;
            int r0 = mc * 128 + pwm * 32 + mi * 16 + (ln >> 2);
            int r1 = r0 + 8;
            int kb = ks * 16 + (ln & 3) * 2;
            uint4 q;
            q.x = pack_bf16x2(feat[r0 * FF + kb],     feat[r0 * FF + kb + 1]);
            q.y = pack_bf16x2(feat[r1 * FF + kb],     feat[r1 * FF + kb + 1]);
            q.z = pack_bf16x2(feat[r0 * FF + kb + 8], feat[r0 * FF + kb + 9]);
            q.w = pack_bf16x2(feat[r1 * FF + kb + 8], feat[r1 * FF + kb + 9]);
            g_Apack[i] = q;
        }
    }
    // ---- aux: exact-fp32 target-column math (CTAs 0..127, 4 warps each) ----
    if (bid < 128 && wid < 4) {
        int b = bid * 4 + wid;
        int t = load_target(target, b, C);
        float fsq = 0.f, wsq = 0.f, dot = 0.f;
        #pragma unroll
        for (int q = 0; q < 4; q++) {
            int f = lane + q * 32;
            float fv = feat[b * FF + f];
            float wv = w[(size_t)f * (size_t)C + (size_t)t];
            fsq = fmaf(fv, fv, fsq);
            wsq = fmaf(wv, wv, wsq);
            dot = fmaf(fv, wv, dot);
        }
        const unsigned msk = 0xffffffffu;
        #pragma unroll
        for (int o = 16; o > 0; o >>= 1) {
            fsq += __shfl_down_sync(msk, fsq, o);
            wsq += __shfl_down_sync(msk, wsq, o);
            dot += __shfl_down_sync(msk, dot, o);
        }
        if (lane == 0) {
            float modulus = sqrtf(fsq) * sqrtf(wsq);
            float ct = dot / (modulus * 1.01f);
            ct = fminf(1.0f, fmaxf(-1.0f, ct));
            float ml = modulus * cosf(acosf(ct) + 0.5f);  // ANGLE=0.5
            g_margin[b] = ml;
            g_adj[b] = expf(ml) - expf(dot);
        }
    }
    // ---- start-of-kernel grid barrier: Apack visible everywhere ----
    __syncthreads();
    if (tid == 0) {
        __threadfence();                              // release Apack writes
        atomicAdd((unsigned*)&g_cnt0, 1u);
        while (g_cnt0 < (unsigned)NCTA) __nanosleep(64);
        __threadfence();                              // acquire
    }
    __syncthreads();

    // B fragment lane base (proven mapping, BSTRIDE=272, wn in {0,1})
    const uint32_t b_lb = (uint32_t)((((lane >> 3) & 1) * 8 + (lane & 7)) * BSTRIDE
                          + (((uint32_t)(wn * 128 + ((lane >> 4) << 4)))
                             ^ (uint32_t)(((lane >> 3) & 1) << 4)));

    const uint4* __restrict__ Ap = g_Apack;

    int cur = 0;
    for (int it = 0; it < niter; it++) {
        const int bx = bid + it * NCTA;
        const bool have_next = (it + 1 < niter);
        const int nc0 = (bx + NCTA) * BN;
        const uint32_t bbase = sb + SM_B + cur * BSZ;

        for (int m = 0; m < 4; m++) {
            float4 vh[4];
            if (have_next)
                ldg_B(vh, w, m, nc0, C, tid);    // LDG early: lands behind MMA

            const int qb = m * 2048 + wm * 512 + lane;

            float acc[2][8][4];
            #pragma unroll
            for (int mi = 0; mi < 2; mi++)
                #pragma unroll
                for (int j = 0; j < 8; j++)
                    #pragma unroll
                    for (int q = 0; q < 4; q++) acc[mi][j][q] = 0.0f;

            #pragma unroll
            for (int ks = 0; ks < 8; ks++) {
                uint4 af0 = Ap[qb + ks * 32];         // mi=0 fragment quad
                uint4 af1 = Ap[qb + 256 + ks * 32];   // mi=1 fragment quad
                #pragma unroll
                for (int np = 0; np < 4; np++) {
                    uint32_t bfr[4];
                    ldsm4t(bfr, bbase + b_lb + ks * 16 * BSTRIDE + np * 32);
                    mma4(acc[0][np * 2 + 0], af0.x, af0.y, af0.z, af0.w, bfr[0], bfr[1]);
                    mma4(acc[0][np * 2 + 1], af0.x, af0.y, af0.z, af0.w, bfr[2], bfr[3]);
                    mma4(acc[1][np * 2 + 0], af1.x, af1.y, af1.z, af1.w, bfr[0], bfr[1]);
                    mma4(acc[1][np * 2 + 1], af1.x, af1.y, af1.z, af1.w, bfr[2], bfr[3]);
                }
            }

            // epilogue: exp 87.5% MUFU / 12.5% FMA-poly + warp row-sums -> STG
            const unsigned msk = 0xffffffffu;
            float* slot = &g_part[(size_t)(bx * 2 + wn) * 512];
            #pragma unroll
            for (int mi = 0; mi < 2; mi++) {
                float s0 = 0.f, s1 = 0.f;
                #pragma unroll
                for (int j = 0; j < 8; j++) {
                    s0 += __expf(acc[mi][j][0]);      // MUFU
                    s0 += __expf(acc[mi][j][1]);      // MUFU
                    s1 += __expf(acc[mi][j][2]);      // MUFU
                    if (j & 1) s1 += fast_exp(acc[mi][j][3]);  // poly (12.5%)
                    else       s1 += __expf(acc[mi][j][3]);
                }
                s0 += __shfl_xor_sync(msk, s0, 1);
                s0 += __shfl_xor_sync(msk, s0, 2);
                s1 += __shfl_xor_sync(msk, s1, 1);
                s1 += __shfl_xor_sync(msk, s1, 2);
                if ((lane & 3) == 0) {
                    int g = lane >> 2;
                    int grow = m * 128 + wm * 32 + mi * 16 + g;
                    slot[grow]     = s0;
                    slot[grow + 8] = s1;
                }
            }

            if (have_next)
                sts_B(vh, smem, cur ^ 1, m, tid);    // STS late: data long arrived
        }
        __syncthreads();                  // ONE barrier per tile (B swap)
        cur ^= 1;
    }
}

// ================= finalize (merged): per-row value + last-block scalar ====
__global__ void finalize_kernel(int NSLOT, float pad, float* __restrict__ out) {
    int row = blockIdx.x;        // 0..511
    int j = threadIdx.x;         // 0..127
    float s = 0.f;
    for (int t = j; t < NSLOT; t += 128)      // fixed order -> deterministic
        s += g_part[(size_t)t * 512 + row];
    __shared__ float red[128];
    __shared__ bool last;
    red[j] = s;
    __syncthreads();
    #pragma unroll
    for (int o = 64; o > 0; o >>= 1) {
        if (j < o) red[j] += red[j + o];
        __syncthreads();
    }
    if (j == 0) {
        float down = red[0] - pad + g_adj[row];
        g_rowv[row] = logf(down) - g_margin[row];
        __threadfence();                          // release g_rowv[row]
        unsigned t = atomicAdd(&g_fincnt, 1u);
        last = (t == (unsigned)(BB - 1));
    }
    __syncthreads();
    if (!last) return;
    __threadfence();                              // acquire all g_rowv

    float v = (g_rowv[j] + g_rowv[j + 128]) + (g_rowv[j + 256] + g_rowv[j + 384]);
    red[j] = v;
    __syncthreads();
    #pragma unroll
    for (int o = 64; o > 0; o >>= 1) {
        if (j < o) red[j] += red[j + o];
        __syncthreads();
    }
    if (j == 0) {
        out[0] = red[0] / (float)BB;
        g_fincnt = 0;                             // reset for graph replay
        g_cnt0 = 0;                               // reset start barrier too
        __threadfence();
    }
}

// ================= launch =================
extern "C" void kernel_launch(void* const* d_in, const int* in_sizes, int n_in,
                              void* d_out, int out_size) {
    const float* feat = (const float*)d_in[0];
    const float* w    = (const float*)d_in[1];
    const void*  target = d_in[2];
    float* out = (float*)d_out;

    int C  = in_sizes[1] / FF;               // 100000
    int NT = (C + BN - 1) / BN;              // 782
    float pad = (float)(NT * BN - C);        // 96

    cudaFuncSetAttribute(fused_kernel,
                         cudaFuncAttributeMaxDynamicSharedMemorySize, SM_TOTAL);

    fused_kernel<<<NCTA, 256, SM_TOTAL>>>(feat, w, target, C, NT);
    finalize_kernel<<<BB, 128>>>(2 * NT, pad, out);
}